// round 1
// baseline (speedup 1.0000x reference)
#include <cuda_runtime.h>
#include <math.h>

#define HH 12
#define NP 196
#define FF 8
#define DIMM 768
#define D3 192
#define BB 8
#define SS 1569
#define PP 195
#define C3 2304
#define SCALE_INV (1.0f/96.0f)

// ---------------- scratch (device globals; no allocation allowed) ----------
__device__ float g_xq[BB*SS*C3];     // x @ Wq + bq   (full 1569 tokens)
__device__ float g_xk[BB*SS*C3];     // x @ Wk + bk
__device__ float g_xv[BB*SS*C3];     // x @ Wv + bv
__device__ float g_t1[BB*PP*C3];     // merged temporal-attn result, 195 unique rows/b
__device__ float g_ti[BB*PP*DIMM];   // t1 @ Wt + bt
__device__ float g_q2[BB*PP*C3];     // ti @ Wq
__device__ float g_k2[BB*PP*C3];     // ti @ Wv  (reference: k2 = _heads(ti @ Wv))
__device__ float g_v2[BB*PP*C3];     // ti @ Wk  (reference: v2 = _heads(ti @ Wk))
__device__ float g_cls[BB*C3];       // inter_cls merged
__device__ float g_t2[BB*FF*C3];     // 8 output-attention rows per batch (merged)
__device__ float g_rows[BB*9*DIMM];  // 9 final distinct output rows per batch

// ---------------- tiled fp32 GEMM: C = A(MxK) @ B(KxN) + bias ----------------
// BM=BN=128, BK=16, 256 threads, 8x8 per thread. K%16==0, N%128==0 assumed.
__global__ void gemm128(const float* __restrict__ A, const float* __restrict__ Bm,
                        const float* __restrict__ bias, float* __restrict__ C,
                        int M, int N, int K) {
    __shared__ float As[16*128];   // [k][m]
    __shared__ float Bs[16*128];   // [k][n]
    const int tid = threadIdx.x;
    const int bx = blockIdx.x, by = blockIdx.y;
    const int tx = tid & 15, ty = tid >> 4;
    float acc[8][8];
#pragma unroll
    for (int i = 0; i < 8; i++)
#pragma unroll
        for (int j = 0; j < 8; j++) acc[i][j] = 0.f;

    const int rowA = by * 128;
    for (int k0 = 0; k0 < K; k0 += 16) {
#pragma unroll
        for (int it = 0; it < 2; it++) {
            int f = tid + 256 * it;
            int r = f >> 2, c4 = f & 3;
            int gr = rowA + r;
            float4 v = make_float4(0.f, 0.f, 0.f, 0.f);
            if (gr < M) v = *(const float4*)(A + (size_t)gr * K + k0 + c4 * 4);
            As[(c4*4+0)*128 + r] = v.x;
            As[(c4*4+1)*128 + r] = v.y;
            As[(c4*4+2)*128 + r] = v.z;
            As[(c4*4+3)*128 + r] = v.w;
        }
#pragma unroll
        for (int it = 0; it < 2; it++) {
            int f = tid + 256 * it;
            int r = f >> 5, c4 = f & 31;
            float4 v = *(const float4*)(Bm + (size_t)(k0 + r) * N + bx * 128 + c4 * 4);
            *(float4*)(Bs + r * 128 + c4 * 4) = v;
        }
        __syncthreads();
#pragma unroll
        for (int k = 0; k < 16; k++) {
            float a[8], b[8];
#pragma unroll
            for (int i = 0; i < 8; i++) a[i] = As[k*128 + ty*8 + i];
#pragma unroll
            for (int j = 0; j < 8; j++) b[j] = Bs[k*128 + tx*8 + j];
#pragma unroll
            for (int i = 0; i < 8; i++)
#pragma unroll
                for (int j = 0; j < 8; j++) acc[i][j] += a[i] * b[j];
        }
        __syncthreads();
    }
#pragma unroll
    for (int i = 0; i < 8; i++) {
        int m = rowA + ty * 8 + i;
        if (m >= M) continue;
#pragma unroll
        for (int j = 0; j < 8; j += 4) {
            int n = bx * 128 + tx * 8 + j;
            float4 v;
            v.x = acc[i][j+0] + bias[n+0];
            v.y = acc[i][j+1] + bias[n+1];
            v.z = acc[i][j+2] + bias[n+2];
            v.w = acc[i][j+3] + bias[n+3];
            *(float4*)(C + (size_t)m * N + n) = v;
        }
    }
}

// ---------------- inter_cls: 1 query (cls, Wq) over all 1569 tokens ----------
// grid(12, 8) = (h, b); 256 threads
__global__ void inter_cls_kernel() {
    __shared__ float sc[SS];
    __shared__ float red[256];
    const int h = blockIdx.x, b = blockIdx.y;
    const int tid = threadIdx.x, lane = tid & 31, wid = tid >> 5;
    const float* baseq = g_xq + (size_t)b * SS * C3 + h * D3;
    const float* basek = g_xk + (size_t)b * SS * C3 + h * D3;
    const float* basev = g_xv + (size_t)b * SS * C3 + h * D3;

    float qv[6];
#pragma unroll
    for (int i = 0; i < 6; i++) qv[i] = baseq[lane + 32 * i];

    for (int t = wid; t < SS; t += 8) {
        const float* kr = basek + (size_t)t * C3;
        float p = 0.f;
#pragma unroll
        for (int i = 0; i < 6; i++) p += qv[i] * kr[lane + 32 * i];
#pragma unroll
        for (int off = 16; off; off >>= 1) p += __shfl_xor_sync(0xffffffffu, p, off);
        if (lane == 0) sc[t] = p * SCALE_INV;
    }
    __syncthreads();

    float m = -1e30f;
    for (int t = tid; t < SS; t += 256) m = fmaxf(m, sc[t]);
    red[tid] = m; __syncthreads();
    for (int s = 128; s; s >>= 1) { if (tid < s) red[tid] = fmaxf(red[tid], red[tid+s]); __syncthreads(); }
    m = red[0]; __syncthreads();

    float z = 0.f;
    for (int t = tid; t < SS; t += 256) { float e = expf(sc[t] - m); sc[t] = e; z += e; }
    red[tid] = z; __syncthreads();
    for (int s = 128; s; s >>= 1) { if (tid < s) red[tid] += red[tid+s]; __syncthreads(); }
    float invZ = 1.f / red[0];

    if (tid < D3) {
        float a0 = 0.f, a1 = 0.f;
        int t = 0;
        for (; t + 1 < SS; t += 2) {
            a0 += sc[t]   * basev[(size_t)t     * C3 + tid];
            a1 += sc[t+1] * basev[(size_t)(t+1) * C3 + tid];
        }
        if (t < SS) a0 += sc[t] * basev[(size_t)t * C3 + tid];
        g_cls[b * C3 + h * D3 + tid] = (a0 + a1) * invZ;
    }
}

// ---------------- temporal attention per patch (8x8 over frames) -------------
// grid(195, 12, 8) = (p, h, b); 192 threads
__global__ void temporal_kernel() {
    __shared__ float qs[8*193];
    __shared__ float ks[8*193];
    __shared__ float sc[8*9];
    __shared__ float cw[8];
    const int p = blockIdx.x, h = blockIdx.y, b = blockIdx.z;
    const int tid = threadIdx.x;
    const size_t bb = (size_t)b * SS * C3;

    for (int e = tid; e < 8 * D3; e += 192) {
        int f = e / D3, j = e - f * D3;
        int tok = f * NP + p + 2;   // x token index: 1 + f*196 + (p+1)
        qs[f*193 + j] = g_xq[bb + (size_t)tok * C3 + h * D3 + j];
        ks[f*193 + j] = g_xv[bb + (size_t)tok * C3 + h * D3 + j];  // k5 from km (Wv)
    }
    __syncthreads();

    if (tid < 64) {
        int f = tid >> 3, g = tid & 7;
        float s = 0.f;
        for (int j = 0; j < D3; j++) s += qs[f*193 + j] * ks[g*193 + j];
        sc[f*9 + g] = s * SCALE_INV;
    }
    __syncthreads();

    if (tid < 8) {
        int f = tid;
        float mx = -1e30f;
        for (int g = 0; g < 8; g++) mx = fmaxf(mx, sc[f*9+g]);
        float z = 0.f;
        for (int g = 0; g < 8; g++) { float e = expf(sc[f*9+g] - mx); sc[f*9+g] = e; z += e; }
        float inv = 1.f / z;
        for (int g = 0; g < 8; g++) sc[f*9+g] *= inv;
    }
    __syncthreads();
    if (tid < 8) {
        int g = tid;
        float s = 0.f;
        for (int f = 0; f < 8; f++) s += sc[f*9+g];
        cw[g] = s;
    }
    __syncthreads();

    // t1[d] = sum_g cw[g] * v5[g,d];  v5 from vm (Wk)
    {
        int d = tid;
        float acc = 0.f;
#pragma unroll
        for (int g = 0; g < 8; g++) {
            int tok = g * NP + p + 2;
            acc += cw[g] * g_xk[bb + (size_t)tok * C3 + h * D3 + d];
        }
        g_t1[((size_t)b * PP + p) * C3 + h * D3 + d] = acc;
    }
}

// ---------------- output-stage attention (column-weight trick) ---------------
// grid(nxi, 12, 8); 256 threads; dynamic smem: Kb[nk*193] | qb[8*192] | w[nk]
__global__ void out_attn_kernel(int xi_base, int nk) {
    extern __shared__ float sm[];
    float* Kb = sm;
    float* qb = sm + nk * 193;
    float* w  = qb + 8 * D3;
    const int xi = xi_base + blockIdx.x;
    const int h = blockIdx.y, b = blockIdx.z;
    const int tid = threadIdx.x, lane = tid & 31, wid = tid >> 5;
    const size_t rbase = (size_t)b * PP * C3 + h * D3;

    for (int e = tid; e < nk * D3; e += 256) {
        int r = e / D3, j = e - r * D3;
        int kp = (nk == 196) ? (r % PP) : (xi + r);
        Kb[r*193 + j] = g_k2[rbase + (size_t)kp * C3 + j];
    }
    for (int k = tid; k < nk; k += 256) w[k] = 0.f;
    __syncthreads();

    for (int q = wid; q < 196; q += 8) {
        int qp = (xi + q) % PP;
        for (int j = lane; j < D3; j += 32)
            qb[wid * D3 + j] = g_q2[rbase + (size_t)qp * C3 + j];
        __syncwarp();

        float s[7];
        int cnt = 0;
        for (int k = lane; k < nk; k += 32) {
            float d = 0.f;
            const float* kr = Kb + k * 193;
            const float* qr = qb + wid * D3;
            for (int j = 0; j < D3; j++) d += qr[j] * kr[j];
            s[cnt++] = d * SCALE_INV;
        }
        float mx = -1e30f;
        for (int c = 0; c < cnt; c++) mx = fmaxf(mx, s[c]);
#pragma unroll
        for (int off = 16; off; off >>= 1) mx = fmaxf(mx, __shfl_xor_sync(0xffffffffu, mx, off));
        float z = 0.f;
        for (int c = 0; c < cnt; c++) { float e = expf(s[c] - mx); s[c] = e; z += e; }
#pragma unroll
        for (int off = 16; off; off >>= 1) z += __shfl_xor_sync(0xffffffffu, z, off);
        float inv = 1.f / z;
        int c = 0;
        for (int k = lane; k < nk; k += 32, c++) atomicAdd(&w[k], s[c] * inv);
        __syncwarp();
    }
    __syncthreads();

    if (tid < D3) {
        float acc = 0.f;
        for (int k = 0; k < nk; k++) {
            int kp = (nk == 196) ? (k % PP) : (xi + k);
            acc += w[k] * g_v2[rbase + (size_t)kp * C3 + tid];
        }
        g_t2[((size_t)b * FF + xi) * C3 + h * D3 + tid] = acc;
    }
}

// ---------------- final 9 rows per batch: A(9x2304) @ Wf + bf ----------------
// grid(4, 8) = (col-block, b); 192 threads; dyn smem 9*2304 floats
__global__ void final_rows_kernel(const float* __restrict__ Wf, const float* __restrict__ bf) {
    extern __shared__ float As[];
    const int cb = blockIdx.x, b = blockIdx.y;
    const int tid = threadIdx.x;
    for (int e = tid; e < 9 * C3; e += 192) {
        int r = e / C3, k = e - r * C3;
        As[e] = (r == 0) ? g_cls[b * C3 + k] : g_t2[((size_t)b * FF + (r-1)) * C3 + k];
    }
    __syncthreads();
    const int c = cb * 192 + tid;
    float acc[9];
#pragma unroll
    for (int r = 0; r < 9; r++) acc[r] = 0.f;
    for (int k = 0; k < C3; k++) {
        float wv = Wf[(size_t)k * DIMM + c];
#pragma unroll
        for (int r = 0; r < 9; r++) acc[r] += As[r * C3 + k] * wv;
    }
    float bv = bf[c];
#pragma unroll
    for (int r = 0; r < 9; r++)
        g_rows[((size_t)b * 9 + r) * DIMM + c] = acc[r] + bv;
}

// ---------------- broadcast 9 rows -> (B, 1569, 768) output -----------------
__global__ void bcast_kernel(float* __restrict__ out) {
    size_t idx = (size_t)blockIdx.x * blockDim.x + threadIdx.x;
    const size_t total = (size_t)BB * SS * DIMM;
    if (idx >= total) return;
    int c = idx % DIMM;
    size_t rs = idx / DIMM;
    int s = rs % SS;
    int b = rs / SS;
    int r = (s == 0) ? 0 : 1 + ((s - 1) & 7);
    out[idx] = g_rows[((size_t)b * 9 + r) * DIMM + c];
}

// ---------------- launch ------------------------------------------------------
extern "C" void kernel_launch(void* const* d_in, const int* in_sizes, int n_in,
                              void* d_out, int out_size) {
    const float* x  = (const float*)d_in[0];
    const float* Wq = (const float*)d_in[1];
    const float* bq = (const float*)d_in[2];
    const float* Wk = (const float*)d_in[3];
    const float* bk = (const float*)d_in[4];
    const float* Wv = (const float*)d_in[5];
    const float* bv = (const float*)d_in[6];
    const float* Wt = (const float*)d_in[7];
    const float* bt = (const float*)d_in[8];
    const float* Wf = (const float*)d_in[9];
    const float* bf = (const float*)d_in[10];
    float* out = (float*)d_out;

    float *p_xq, *p_xk, *p_xv, *p_t1, *p_ti, *p_q2, *p_k2, *p_v2;
    cudaGetSymbolAddress((void**)&p_xq, g_xq);
    cudaGetSymbolAddress((void**)&p_xk, g_xk);
    cudaGetSymbolAddress((void**)&p_xv, g_xv);
    cudaGetSymbolAddress((void**)&p_t1, g_t1);
    cudaGetSymbolAddress((void**)&p_ti, g_ti);
    cudaGetSymbolAddress((void**)&p_q2, g_q2);
    cudaGetSymbolAddress((void**)&p_k2, g_k2);
    cudaGetSymbolAddress((void**)&p_v2, g_v2);

    // opt-in shared memory sizes (idempotent, not stream ops)
    cudaFuncSetAttribute(out_attn_kernel, cudaFuncAttributeMaxDynamicSharedMemorySize, 160000);
    cudaFuncSetAttribute(final_rows_kernel, cudaFuncAttributeMaxDynamicSharedMemorySize, 9*C3*4);

    const int M1 = BB * SS;   // 12552
    // 1-3: QKV projections of x
    {
        dim3 grid(C3/128, (M1 + 127)/128);
        gemm128<<<grid, 256>>>(x, Wq, bq, p_xq, M1, C3, DIMM);
        gemm128<<<grid, 256>>>(x, Wk, bk, p_xk, M1, C3, DIMM);
        gemm128<<<grid, 256>>>(x, Wv, bv, p_xv, M1, C3, DIMM);
    }
    // cls attention + temporal attention
    inter_cls_kernel<<<dim3(HH, BB), 256>>>();
    temporal_kernel<<<dim3(PP, HH, BB), 192>>>();

    // ti = t1 @ Wt + bt   (1560 x 2304 @ 2304 x 768)
    {
        const int M = BB * PP;
        dim3 grid(DIMM/128, (M + 127)/128);
        gemm128<<<grid, 256>>>(p_t1, Wt, bt, p_ti, M, DIMM, C3);
    }
    // q2/k2/v2 = ti @ {Wq, Wv, Wk}
    {
        const int M = BB * PP;
        dim3 grid(C3/128, (M + 127)/128);
        gemm128<<<grid, 256>>>(p_ti, Wq, bq, p_q2, M, C3, DIMM);
        gemm128<<<grid, 256>>>(p_ti, Wv, bv, p_k2, M, C3, DIMM);  // k2 = Wv proj
        gemm128<<<grid, 256>>>(p_ti, Wk, bk, p_v2, M, C3, DIMM);  // v2 = Wk proj
    }
    // output attentions
    {
        size_t smA = (size_t)(196*193 + 8*D3 + 196) * 4;
        out_attn_kernel<<<dim3(1, HH, BB), 256, smA>>>(0, 196);
        size_t smB = (size_t)(8*193 + 8*D3 + 8) * 4;
        out_attn_kernel<<<dim3(7, HH, BB), 256, smB>>>(1, 8);
    }
    // final rows + broadcast
    final_rows_kernel<<<dim3(4, BB), 192, (size_t)9*C3*4>>>(Wf, bf);
    {
        const size_t total = (size_t)BB * SS * DIMM;
        bcast_kernel<<<(unsigned)((total + 255) / 256), 256>>>(out);
    }
}

// round 3
// speedup vs baseline: 1.3815x; 1.3815x over previous
#include <cuda_runtime.h>
#include <cuda_bf16.h>
#include <mma.h>
#include <cstdint>
#include <math.h>

using namespace nvcuda;

#define HH 12
#define NP 196
#define FF 8
#define DIMM 768
#define D3 192
#define BB 8
#define SS 1569
#define PP 195
#define C3 2304
#define SCALE_INV (1.0f/96.0f)

// ---------------- scratch (device globals; no allocation allowed) ----------
__device__ float g_xq[BB*SS*C3];
__device__ float g_xk[BB*SS*C3];
__device__ float g_xv[BB*SS*C3];
__device__ float g_t1[BB*PP*C3];
__device__ float g_ti[BB*PP*DIMM];
__device__ float g_q2[BB*PP*C3];
__device__ float g_k2[BB*PP*C3];
__device__ float g_v2[BB*PP*C3];
__device__ float g_cls[BB*C3];
__device__ float g_t2[BB*FF*C3];
__device__ float g_rows[BB*9*DIMM];
// pre-transposed weights [N, K]
__device__ float g_WqT[C3*DIMM];
__device__ float g_WkT[C3*DIMM];
__device__ float g_WvT[C3*DIMM];
__device__ float g_WtT[DIMM*C3];

// ---------------- weight transpose: in [K,N] -> out [N,K] -------------------
__global__ void transpose_k(const float* __restrict__ in, float* __restrict__ out,
                            int K, int N) {
    __shared__ float t[32][33];
    const int n0 = blockIdx.x * 32, k0 = blockIdx.y * 32;
    const int tx = threadIdx.x & 31, ty = threadIdx.x >> 5;
#pragma unroll
    for (int i = 0; i < 32; i += 8)
        t[ty + i][tx] = in[(size_t)(k0 + ty + i) * N + n0 + tx];
    __syncthreads();
#pragma unroll
    for (int i = 0; i < 32; i += 8)
        out[(size_t)(n0 + ty + i) * K + k0 + tx] = t[tx][ty + i];
}

// ================= bf16-split HMMA GEMM: C = A(MxK) @ Bt^T + bias ===========
// Bt is [N,K] row-major. BM=BN=128, BK=32. N%128==0, K%32==0, M guarded.
// 3-pass split: acc += Ahi*Bhi + Ahi*Blo + Alo*Bhi  (fp32 accumulate)
#define LDT 40   // bf16 leading dim with pad (32 data + 8)

__global__ void __launch_bounds__(256, 1)
gemm_wmma(const float* __restrict__ A, const float* __restrict__ Bt,
          const float* __restrict__ bias, float* __restrict__ C,
          int M, int N, int K) {
    extern __shared__ char smem[];
    const int tid = threadIdx.x;
    const int wid = tid >> 5;
    const int wm = wid & 3, wn = wid >> 2;
    const int rowA0 = blockIdx.y * 128;
    const int n0 = blockIdx.x * 128;

    wmma::fragment<wmma::accumulator, 16, 16, 16, float> acc[2][4];
#pragma unroll
    for (int i = 0; i < 2; i++)
#pragma unroll
        for (int j = 0; j < 4; j++) wmma::fill_fragment(acc[i][j], 0.f);

    const int nch = K >> 5;
    float4 ra[4], rb[4];

    auto load_regs = [&](int c) {
#pragma unroll
        for (int i = 0; i < 4; i++) {
            const int f = i * 256 + tid;
            const int r = f >> 3, c4 = f & 7;
            const int gr = rowA0 + r;
            ra[i] = (gr < M) ? *(const float4*)(A + (size_t)gr * K + c * 32 + c4 * 4)
                             : make_float4(0.f, 0.f, 0.f, 0.f);
            rb[i] = *(const float4*)(Bt + (size_t)(n0 + r) * K + c * 32 + c4 * 4);
        }
    };
    auto store_smem = [&](int s) {
        __nv_bfloat16* Ah = (__nv_bfloat16*)smem + (size_t)s * 4 * 128 * LDT;
        __nv_bfloat16* Al = Ah + 128 * LDT;
        __nv_bfloat16* Bh = Al + 128 * LDT;
        __nv_bfloat16* Bl = Bh + 128 * LDT;
#pragma unroll
        for (int i = 0; i < 4; i++) {
            const int f = i * 256 + tid;
            const int r = f >> 3, c4 = f & 7;
            const float* va = (const float*)&ra[i];
            const float* vb = (const float*)&rb[i];
#pragma unroll
            for (int e = 0; e < 4; e += 2) {
                __nv_bfloat16 h0 = __float2bfloat16(va[e]);
                __nv_bfloat16 h1 = __float2bfloat16(va[e + 1]);
                __nv_bfloat16 l0 = __float2bfloat16(va[e]     - __bfloat162float(h0));
                __nv_bfloat16 l1 = __float2bfloat16(va[e + 1] - __bfloat162float(h1));
                *(__nv_bfloat162*)(Ah + r * LDT + c4 * 4 + e) = __nv_bfloat162(h0, h1);
                *(__nv_bfloat162*)(Al + r * LDT + c4 * 4 + e) = __nv_bfloat162(l0, l1);
                h0 = __float2bfloat16(vb[e]);
                h1 = __float2bfloat16(vb[e + 1]);
                l0 = __float2bfloat16(vb[e]     - __bfloat162float(h0));
                l1 = __float2bfloat16(vb[e + 1] - __bfloat162float(h1));
                *(__nv_bfloat162*)(Bh + r * LDT + c4 * 4 + e) = __nv_bfloat162(h0, h1);
                *(__nv_bfloat162*)(Bl + r * LDT + c4 * 4 + e) = __nv_bfloat162(l0, l1);
            }
        }
    };
    auto compute = [&](int s) {
        const __nv_bfloat16* Ah = (const __nv_bfloat16*)smem + (size_t)s * 4 * 128 * LDT;
        const __nv_bfloat16* Al = Ah + 128 * LDT;
        const __nv_bfloat16* Bh = Al + 128 * LDT;
        const __nv_bfloat16* Bl = Bh + 128 * LDT;
#pragma unroll
        for (int kk = 0; kk < 32; kk += 16) {
            wmma::fragment<wmma::matrix_a, 16, 16, 16, __nv_bfloat16, wmma::row_major> ah[2], al[2];
            wmma::fragment<wmma::matrix_b, 16, 16, 16, __nv_bfloat16, wmma::col_major> bh[4], bl[4];
#pragma unroll
            for (int i = 0; i < 2; i++) {
                wmma::load_matrix_sync(ah[i], Ah + (wm * 32 + i * 16) * LDT + kk, LDT);
                wmma::load_matrix_sync(al[i], Al + (wm * 32 + i * 16) * LDT + kk, LDT);
            }
#pragma unroll
            for (int j = 0; j < 4; j++) {
                wmma::load_matrix_sync(bh[j], Bh + (wn * 64 + j * 16) * LDT + kk, LDT);
                wmma::load_matrix_sync(bl[j], Bl + (wn * 64 + j * 16) * LDT + kk, LDT);
            }
#pragma unroll
            for (int i = 0; i < 2; i++)
#pragma unroll
                for (int j = 0; j < 4; j++) {
                    wmma::mma_sync(acc[i][j], ah[i], bh[j], acc[i][j]);
                    wmma::mma_sync(acc[i][j], ah[i], bl[j], acc[i][j]);
                    wmma::mma_sync(acc[i][j], al[i], bh[j], acc[i][j]);
                }
        }
    };

    load_regs(0);
    store_smem(0);
    __syncthreads();
    for (int c = 0; c < nch; c++) {
        if (c + 1 < nch) load_regs(c + 1);
        compute(c & 1);
        if (c + 1 < nch) store_smem((c + 1) & 1);
        __syncthreads();
    }

    // epilogue via smem staging (reuse tile smem)
    float* sC = (float*)smem;
#pragma unroll
    for (int i = 0; i < 2; i++)
#pragma unroll
        for (int j = 0; j < 4; j++)
            wmma::store_matrix_sync(sC + (wm * 32 + i * 16) * 128 + wn * 64 + j * 16,
                                    acc[i][j], 128, wmma::mem_row_major);
    __syncthreads();
#pragma unroll
    for (int i = 0; i < 16; i++) {
        const int f = i * 256 + tid;
        const int r = f >> 5, c4 = f & 31;
        const int gm = rowA0 + r;
        if (gm < M) {
            float4 v = *(float4*)(sC + r * 128 + c4 * 4);
            const int n = n0 + c4 * 4;
            v.x += bias[n + 0];
            v.y += bias[n + 1];
            v.z += bias[n + 2];
            v.w += bias[n + 3];
            *(float4*)(C + (size_t)gm * N + n) = v;
        }
    }
}

// ---------------- inter_cls: 1 query (cls, Wq) over all 1569 tokens ----------
__global__ void inter_cls_kernel() {
    __shared__ float sc[SS];
    __shared__ float red[256];
    __shared__ float part[8 * D3];
    const int h = blockIdx.x, b = blockIdx.y;
    const int tid = threadIdx.x, lane = tid & 31, wid = tid >> 5;
    const float* baseq = g_xq + (size_t)b * SS * C3 + h * D3;
    const float* basek = g_xk + (size_t)b * SS * C3 + h * D3;
    const float* basev = g_xv + (size_t)b * SS * C3 + h * D3;

    float qv[6];
#pragma unroll
    for (int i = 0; i < 6; i++) qv[i] = baseq[lane + 32 * i];

    for (int t = wid; t < SS; t += 8) {
        const float* kr = basek + (size_t)t * C3;
        float p = 0.f;
#pragma unroll
        for (int i = 0; i < 6; i++) p += qv[i] * kr[lane + 32 * i];
#pragma unroll
        for (int off = 16; off; off >>= 1) p += __shfl_xor_sync(0xffffffffu, p, off);
        if (lane == 0) sc[t] = p * SCALE_INV;
    }
    __syncthreads();

    float m = -1e30f;
    for (int t = tid; t < SS; t += 256) m = fmaxf(m, sc[t]);
    red[tid] = m; __syncthreads();
    for (int s = 128; s; s >>= 1) { if (tid < s) red[tid] = fmaxf(red[tid], red[tid + s]); __syncthreads(); }
    m = red[0]; __syncthreads();

    float z = 0.f;
    for (int t = tid; t < SS; t += 256) { float e = expf(sc[t] - m); sc[t] = e; z += e; }
    red[tid] = z; __syncthreads();
    for (int s = 128; s; s >>= 1) { if (tid < s) red[tid] += red[tid + s]; __syncthreads(); }
    const float invZ = 1.f / red[0];
    __syncthreads();

    // V accumulation split over 8 warps
    float a[6] = {0.f, 0.f, 0.f, 0.f, 0.f, 0.f};
    for (int t = wid; t < SS; t += 8) {
        const float p = sc[t];
        const float* vr = basev + (size_t)t * C3;
#pragma unroll
        for (int i = 0; i < 6; i++) a[i] += p * vr[lane + 32 * i];
    }
#pragma unroll
    for (int i = 0; i < 6; i++) part[wid * D3 + lane + 32 * i] = a[i];
    __syncthreads();
    if (tid < D3) {
        float s = 0.f;
#pragma unroll
        for (int w = 0; w < 8; w++) s += part[w * D3 + tid];
        g_cls[b * C3 + h * D3 + tid] = s * invZ;
    }
}

// ---------------- temporal attention per patch (8x8 over frames) -------------
__global__ void temporal_kernel() {
    __shared__ float qs[8 * 193];
    __shared__ float ks[8 * 193];
    __shared__ float sc[8 * 9];
    __shared__ float cw[8];
    const int p = blockIdx.x, h = blockIdx.y, b = blockIdx.z;
    const int tid = threadIdx.x;
    const size_t bb = (size_t)b * SS * C3;

    for (int e = tid; e < 8 * D3; e += 192) {
        int f = e / D3, j = e - f * D3;
        int tok = f * NP + p + 2;
        qs[f * 193 + j] = g_xq[bb + (size_t)tok * C3 + h * D3 + j];
        ks[f * 193 + j] = g_xv[bb + (size_t)tok * C3 + h * D3 + j];
    }
    __syncthreads();

    if (tid < 64) {
        int f = tid >> 3, g = tid & 7;
        float s = 0.f;
        for (int j = 0; j < D3; j++) s += qs[f * 193 + j] * ks[g * 193 + j];
        sc[f * 9 + g] = s * SCALE_INV;
    }
    __syncthreads();

    if (tid < 8) {
        int f = tid;
        float mx = -1e30f;
        for (int g = 0; g < 8; g++) mx = fmaxf(mx, sc[f * 9 + g]);
        float z = 0.f;
        for (int g = 0; g < 8; g++) { float e = expf(sc[f * 9 + g] - mx); sc[f * 9 + g] = e; z += e; }
        float inv = 1.f / z;
        for (int g = 0; g < 8; g++) sc[f * 9 + g] *= inv;
    }
    __syncthreads();
    if (tid < 8) {
        int g = tid;
        float s = 0.f;
        for (int f = 0; f < 8; f++) s += sc[f * 9 + g];
        cw[g] = s;
    }
    __syncthreads();

    {
        int d = tid;
        float acc = 0.f;
#pragma unroll
        for (int g = 0; g < 8; g++) {
            int tok = g * NP + p + 2;
            acc += cw[g] * g_xk[bb + (size_t)tok * C3 + h * D3 + d];
        }
        g_t1[((size_t)b * PP + p) * C3 + h * D3 + d] = acc;
    }
}

// ---------------- output-stage attention (column-weight trick) ---------------
__global__ void out_attn_kernel(int xi_base, int nk) {
    extern __shared__ float sm[];
    float* Kb = sm;
    float* qb = sm + nk * 193;
    float* w  = qb + 8 * D3;
    const int xi = xi_base + blockIdx.x;
    const int h = blockIdx.y, b = blockIdx.z;
    const int tid = threadIdx.x, lane = tid & 31, wid = tid >> 5;
    const size_t rbase = (size_t)b * PP * C3 + h * D3;

    for (int e = tid; e < nk * D3; e += 256) {
        int r = e / D3, j = e - r * D3;
        int kp = (nk == 196) ? (r % PP) : (xi + r);
        Kb[r * 193 + j] = g_k2[rbase + (size_t)kp * C3 + j];
    }
    for (int k = tid; k < nk; k += 256) w[k] = 0.f;
    __syncthreads();

    for (int q = wid; q < 196; q += 8) {
        int qp = (xi + q) % PP;
        for (int j = lane; j < D3; j += 32)
            qb[wid * D3 + j] = g_q2[rbase + (size_t)qp * C3 + j];
        __syncwarp();

        float s[7];
        int cnt = 0;
        for (int k = lane; k < nk; k += 32) {
            float d = 0.f;
            const float* kr = Kb + k * 193;
            const float* qr = qb + wid * D3;
            for (int j = 0; j < D3; j++) d += qr[j] * kr[j];
            s[cnt++] = d * SCALE_INV;
        }
        float mx = -1e30f;
        for (int c = 0; c < cnt; c++) mx = fmaxf(mx, s[c]);
#pragma unroll
        for (int off = 16; off; off >>= 1) mx = fmaxf(mx, __shfl_xor_sync(0xffffffffu, mx, off));
        float z = 0.f;
        for (int c = 0; c < cnt; c++) { float e = expf(s[c] - mx); s[c] = e; z += e; }
#pragma unroll
        for (int off = 16; off; off >>= 1) z += __shfl_xor_sync(0xffffffffu, z, off);
        float inv = 1.f / z;
        int c = 0;
        for (int k = lane; k < nk; k += 32, c++) atomicAdd(&w[k], s[c] * inv);
        __syncwarp();
    }
    __syncthreads();

    if (tid < D3) {
        float acc = 0.f;
        for (int k = 0; k < nk; k++) {
            int kp = (nk == 196) ? (k % PP) : (xi + k);
            acc += w[k] * g_v2[rbase + (size_t)kp * C3 + tid];
        }
        g_t2[((size_t)b * FF + xi) * C3 + h * D3 + tid] = acc;
    }
}

// ---------------- final 9 rows per batch: A(9x2304) @ Wf + bf ----------------
__global__ void final_rows_kernel(const float* __restrict__ Wf, const float* __restrict__ bf) {
    extern __shared__ float As[];
    const int cb = blockIdx.x, b = blockIdx.y;
    const int tid = threadIdx.x;
    for (int e = tid; e < 9 * C3; e += 192) {
        int r = e / C3, k = e - r * C3;
        As[e] = (r == 0) ? g_cls[b * C3 + k] : g_t2[((size_t)b * FF + (r - 1)) * C3 + k];
    }
    __syncthreads();
    const int c = cb * 192 + tid;
    float acc[9];
#pragma unroll
    for (int r = 0; r < 9; r++) acc[r] = 0.f;
    for (int k = 0; k < C3; k++) {
        float wv = Wf[(size_t)k * DIMM + c];
#pragma unroll
        for (int r = 0; r < 9; r++) acc[r] += As[r * C3 + k] * wv;
    }
    float bv = bf[c];
#pragma unroll
    for (int r = 0; r < 9; r++)
        g_rows[((size_t)b * 9 + r) * DIMM + c] = acc[r] + bv;
}

// ---------------- broadcast 9 rows -> (B, 1569, 768) output -----------------
__global__ void bcast_kernel(float* __restrict__ out) {
    size_t idx = (size_t)blockIdx.x * blockDim.x + threadIdx.x;
    const size_t total = (size_t)BB * SS * DIMM;
    if (idx >= total) return;
    int c = idx % DIMM;
    size_t rs = idx / DIMM;
    int s = rs % SS;
    int b = rs / SS;
    int r = (s == 0) ? 0 : 1 + ((s - 1) & 7);
    out[idx] = g_rows[((size_t)b * 9 + r) * DIMM + c];
}

// ---------------- launch ------------------------------------------------------
extern "C" void kernel_launch(void* const* d_in, const int* in_sizes, int n_in,
                              void* d_out, int out_size) {
    const float* x  = (const float*)d_in[0];
    const float* Wq = (const float*)d_in[1];
    const float* bq = (const float*)d_in[2];
    const float* Wk = (const float*)d_in[3];
    const float* bk = (const float*)d_in[4];
    const float* Wv = (const float*)d_in[5];
    const float* bv = (const float*)d_in[6];
    const float* Wt = (const float*)d_in[7];
    const float* bt = (const float*)d_in[8];
    const float* Wf = (const float*)d_in[9];
    const float* bf = (const float*)d_in[10];
    float* out = (float*)d_out;

    float *p_xq, *p_xk, *p_xv, *p_t1, *p_ti, *p_q2, *p_k2, *p_v2;
    float *p_WqT, *p_WkT, *p_WvT, *p_WtT;
    cudaGetSymbolAddress((void**)&p_xq, g_xq);
    cudaGetSymbolAddress((void**)&p_xk, g_xk);
    cudaGetSymbolAddress((void**)&p_xv, g_xv);
    cudaGetSymbolAddress((void**)&p_t1, g_t1);
    cudaGetSymbolAddress((void**)&p_ti, g_ti);
    cudaGetSymbolAddress((void**)&p_q2, g_q2);
    cudaGetSymbolAddress((void**)&p_k2, g_k2);
    cudaGetSymbolAddress((void**)&p_v2, g_v2);
    cudaGetSymbolAddress((void**)&p_WqT, g_WqT);
    cudaGetSymbolAddress((void**)&p_WkT, g_WkT);
    cudaGetSymbolAddress((void**)&p_WvT, g_WvT);
    cudaGetSymbolAddress((void**)&p_WtT, g_WtT);

    const size_t GEMM_SMEM = 2 * 4 * 128 * LDT * sizeof(__nv_bfloat16);  // 81920
    cudaFuncSetAttribute(gemm_wmma, cudaFuncAttributeMaxDynamicSharedMemorySize, (int)GEMM_SMEM);
    cudaFuncSetAttribute(out_attn_kernel, cudaFuncAttributeMaxDynamicSharedMemorySize, 160000);
    cudaFuncSetAttribute(final_rows_kernel, cudaFuncAttributeMaxDynamicSharedMemorySize, 9 * C3 * 4);

    // pre-transpose weights into [N,K]
    transpose_k<<<dim3(C3 / 32, DIMM / 32), 256>>>(Wq, p_WqT, DIMM, C3);
    transpose_k<<<dim3(C3 / 32, DIMM / 32), 256>>>(Wk, p_WkT, DIMM, C3);
    transpose_k<<<dim3(C3 / 32, DIMM / 32), 256>>>(Wv, p_WvT, DIMM, C3);
    transpose_k<<<dim3(DIMM / 32, C3 / 32), 256>>>(Wt, p_WtT, C3, DIMM);

    const int M1 = BB * SS;   // 12552
    {
        dim3 grid(C3 / 128, (M1 + 127) / 128);
        gemm_wmma<<<grid, 256, GEMM_SMEM>>>(x, p_WqT, bq, p_xq, M1, C3, DIMM);
        gemm_wmma<<<grid, 256, GEMM_SMEM>>>(x, p_WkT, bk, p_xk, M1, C3, DIMM);
        gemm_wmma<<<grid, 256, GEMM_SMEM>>>(x, p_WvT, bv, p_xv, M1, C3, DIMM);
    }
    inter_cls_kernel<<<dim3(HH, BB), 256>>>();
    temporal_kernel<<<dim3(PP, HH, BB), 192>>>();

    {
        const int M = BB * PP;  // 1560
        dim3 grid(DIMM / 128, (M + 127) / 128);
        gemm_wmma<<<grid, 256, GEMM_SMEM>>>(p_t1, p_WtT, bt, p_ti, M, DIMM, C3);
    }
    {
        const int M = BB * PP;
        dim3 grid(C3 / 128, (M + 127) / 128);
        gemm_wmma<<<grid, 256, GEMM_SMEM>>>(p_ti, p_WqT, bq, p_q2, M, C3, DIMM);
        gemm_wmma<<<grid, 256, GEMM_SMEM>>>(p_ti, p_WvT, bv, p_k2, M, C3, DIMM);  // k2 = Wv proj
        gemm_wmma<<<grid, 256, GEMM_SMEM>>>(p_ti, p_WkT, bk, p_v2, M, C3, DIMM);  // v2 = Wk proj
    }
    {
        size_t smA = (size_t)(196 * 193 + 8 * D3 + 196) * 4;
        out_attn_kernel<<<dim3(1, HH, BB), 256, smA>>>(0, 196);
        size_t smB = (size_t)(8 * 193 + 8 * D3 + 8) * 4;
        out_attn_kernel<<<dim3(7, HH, BB), 256, smB>>>(1, 8);
    }
    final_rows_kernel<<<dim3(4, BB), 192, (size_t)9 * C3 * 4>>>(Wf, bf);
    {
        const size_t total = (size_t)BB * SS * DIMM;
        bcast_kernel<<<(unsigned)((total + 255) / 256), 256>>>(out);
    }
}

// round 4
// speedup vs baseline: 1.4600x; 1.0568x over previous
#include <cuda_runtime.h>
#include <cuda_bf16.h>
#include <mma.h>
#include <cstdint>
#include <math.h>

using namespace nvcuda;

#define HH 12
#define NP 196
#define FF 8
#define DIMM 768
#define D3 192
#define BB 8
#define SS 1569
#define PP 195
#define C3 2304
#define SCALE_INV (1.0f/96.0f)

#define M1PAD 12672   // ceil(8*1569/128)*128
#define M2PAD 1664    // ceil(8*195/128)*128

// ---------------- scratch (device globals; zero-initialized) ----------------
__device__ float g_xq[BB*SS*C3];
__device__ float g_xk[BB*SS*C3];
__device__ float g_xv[BB*SS*C3];
__device__ float g_t1[BB*PP*C3];
__device__ float g_ti[BB*PP*DIMM];
__device__ float g_q2[BB*PP*C3];
__device__ float g_k2[BB*PP*C3];
__device__ float g_v2[BB*PP*C3];
__device__ float g_cls[BB*C3];
__device__ float g_t2[BB*FF*C3];
__device__ float g_rows[BB*9*DIMM];
// bf16 hi/lo split buffers (A-side, padded rows)
__device__ __nv_bfloat16 g_xhi[M1PAD*DIMM],  g_xlo[M1PAD*DIMM];
__device__ __nv_bfloat16 g_t1hi[M2PAD*C3],   g_t1lo[M2PAD*C3];
__device__ __nv_bfloat16 g_tihi[M2PAD*DIMM], g_tilo[M2PAD*DIMM];
// bf16 hi/lo transposed weights [N,K]
__device__ __nv_bfloat16 g_WqThi[C3*DIMM], g_WqTlo[C3*DIMM];
__device__ __nv_bfloat16 g_WkThi[C3*DIMM], g_WkTlo[C3*DIMM];
__device__ __nv_bfloat16 g_WvThi[C3*DIMM], g_WvTlo[C3*DIMM];
__device__ __nv_bfloat16 g_WtThi[DIMM*C3], g_WtTlo[DIMM*C3];

// ---------------- cp.async helpers ------------------------------------------
__device__ __forceinline__ uint32_t smem_u32(const void* p) {
    uint32_t a;
    asm("{ .reg .u64 t; cvta.to.shared.u64 t, %1; cvt.u32.u64 %0, t; }" : "=r"(a) : "l"(p));
    return a;
}
#define CP_ASYNC16(dst_u32, src_ptr) \
    asm volatile("cp.async.cg.shared.global [%0], [%1], 16;" :: "r"(dst_u32), "l"(src_ptr))
#define CP_COMMIT() asm volatile("cp.async.commit_group;" ::: "memory")
#define CP_WAIT2()  asm volatile("cp.async.wait_group 2;" ::: "memory")

// ---------------- split: fp32 -> bf16 hi + bf16 lo --------------------------
__global__ void split_f32(const float* __restrict__ in, __nv_bfloat16* __restrict__ hi,
                          __nv_bfloat16* __restrict__ lo, int n4) {
    int i = blockIdx.x * blockDim.x + threadIdx.x;
    if (i >= n4) return;
    float4 v = ((const float4*)in)[i];
    __nv_bfloat16 h0 = __float2bfloat16(v.x), h1 = __float2bfloat16(v.y);
    __nv_bfloat16 h2 = __float2bfloat16(v.z), h3 = __float2bfloat16(v.w);
    __nv_bfloat162 lo01(__float2bfloat16(v.x - __bfloat162float(h0)),
                        __float2bfloat16(v.y - __bfloat162float(h1)));
    __nv_bfloat162 lo23(__float2bfloat16(v.z - __bfloat162float(h2)),
                        __float2bfloat16(v.w - __bfloat162float(h3)));
    ((__nv_bfloat162*)hi)[i * 2 + 0] = __nv_bfloat162(h0, h1);
    ((__nv_bfloat162*)hi)[i * 2 + 1] = __nv_bfloat162(h2, h3);
    ((__nv_bfloat162*)lo)[i * 2 + 0] = lo01;
    ((__nv_bfloat162*)lo)[i * 2 + 1] = lo23;
}

// ---------------- transpose + split: fp32 [K,N] -> bf16 hi/lo [N,K] ---------
__global__ void transpose_split(const float* __restrict__ in,
                                __nv_bfloat16* __restrict__ hi,
                                __nv_bfloat16* __restrict__ lo, int K, int N) {
    __shared__ float t[32][33];
    const int n0 = blockIdx.x * 32, k0 = blockIdx.y * 32;
    const int tx = threadIdx.x & 31, ty = threadIdx.x >> 5;
#pragma unroll
    for (int i = 0; i < 32; i += 8)
        t[ty + i][tx] = in[(size_t)(k0 + ty + i) * N + n0 + tx];
    __syncthreads();
#pragma unroll
    for (int i = 0; i < 32; i += 8) {
        float v = t[tx][ty + i];
        __nv_bfloat16 h = __float2bfloat16(v);
        hi[(size_t)(n0 + ty + i) * K + k0 + tx] = h;
        lo[(size_t)(n0 + ty + i) * K + k0 + tx] = __float2bfloat16(v - __bfloat162float(h));
    }
}

// ================= bf16-split HMMA GEMM with cp.async pipeline ==============
// C(MxN) = [Ahi+Alo](MxK) @ [Bhi+Blo]([N,K])^T + bias, 3-pass fp32 accumulate.
// BM=BN=128, BK=32, 3 stages. A buffers padded to 128-row multiple.
#define LDT 40
#define TILE_B (128 * LDT * 2)        // 10240 bytes per bf16 tile
#define STAGE_B (4 * TILE_B)          // 40960 bytes per stage
#define NSTAGE 3

__global__ void __launch_bounds__(256, 1)
gemm_bs(const __nv_bfloat16* __restrict__ Ahi, const __nv_bfloat16* __restrict__ Alo,
        const __nv_bfloat16* __restrict__ Bhi, const __nv_bfloat16* __restrict__ Blo,
        const float* __restrict__ bias, float* __restrict__ C,
        int M, int N, int K) {
    extern __shared__ char smem[];
    const uint32_t smem_b = smem_u32(smem);
    const int tid = threadIdx.x;
    const int wid = tid >> 5;
    const int wm = wid & 3, wn = wid >> 2;
    const int rowA0 = blockIdx.y * 128;
    const int n0 = blockIdx.x * 128;
    const int nch = K >> 5;

    // per-thread cp.async coordinates: 2 ops per tile, 8 ops per stage
    const int r_cp = tid >> 1;              // 0..127
    const int s_cp = (tid & 1) * 2;         // 0 or 2 (two 16B segs each)
    const __nv_bfloat16* srcs[4];
    srcs[0] = Ahi + (size_t)(rowA0 + r_cp) * K;
    srcs[1] = Alo + (size_t)(rowA0 + r_cp) * K;
    srcs[2] = Bhi + (size_t)(n0 + r_cp) * K;
    srcs[3] = Blo + (size_t)(n0 + r_cp) * K;
    const uint32_t dst_row = smem_b + r_cp * (LDT * 2);

    auto issue_stage = [&](int c, int buf) {
        const int k0 = c << 5;
        const uint32_t sb = buf * STAGE_B;
#pragma unroll
        for (int t = 0; t < 4; t++) {
            const __nv_bfloat16* src = srcs[t] + k0 + s_cp * 8;
            const uint32_t dst = dst_row + sb + t * TILE_B + s_cp * 16;
            CP_ASYNC16(dst, src);
            CP_ASYNC16(dst + 16, src + 8);
        }
    };

    wmma::fragment<wmma::accumulator, 16, 16, 16, float> acc[2][4];
#pragma unroll
    for (int i = 0; i < 2; i++)
#pragma unroll
        for (int j = 0; j < 4; j++) wmma::fill_fragment(acc[i][j], 0.f);

    // prologue: stages 0..NSTAGE-2
#pragma unroll
    for (int c = 0; c < NSTAGE - 1; c++) {
        if (c < nch) issue_stage(c, c);
        CP_COMMIT();
    }

    for (int c = 0; c < nch; c++) {
        const int cn = c + NSTAGE - 1;
        if (cn < nch) issue_stage(cn, cn % NSTAGE);
        CP_COMMIT();
        CP_WAIT2();
        __syncthreads();

        const __nv_bfloat16* Ah = (const __nv_bfloat16*)(smem + (c % NSTAGE) * STAGE_B);
        const __nv_bfloat16* Al = Ah + 128 * LDT;
        const __nv_bfloat16* Bh = Al + 128 * LDT;
        const __nv_bfloat16* Bl = Bh + 128 * LDT;
#pragma unroll
        for (int kk = 0; kk < 32; kk += 16) {
            wmma::fragment<wmma::matrix_a, 16, 16, 16, __nv_bfloat16, wmma::row_major> ah[2], al[2];
            wmma::fragment<wmma::matrix_b, 16, 16, 16, __nv_bfloat16, wmma::col_major> bh[4], bl[4];
#pragma unroll
            for (int i = 0; i < 2; i++) {
                wmma::load_matrix_sync(ah[i], Ah + (wm * 32 + i * 16) * LDT + kk, LDT);
                wmma::load_matrix_sync(al[i], Al + (wm * 32 + i * 16) * LDT + kk, LDT);
            }
#pragma unroll
            for (int j = 0; j < 4; j++) {
                wmma::load_matrix_sync(bh[j], Bh + (wn * 64 + j * 16) * LDT + kk, LDT);
                wmma::load_matrix_sync(bl[j], Bl + (wn * 64 + j * 16) * LDT + kk, LDT);
            }
#pragma unroll
            for (int i = 0; i < 2; i++)
#pragma unroll
                for (int j = 0; j < 4; j++) {
                    wmma::mma_sync(acc[i][j], ah[i], bh[j], acc[i][j]);
                    wmma::mma_sync(acc[i][j], ah[i], bl[j], acc[i][j]);
                    wmma::mma_sync(acc[i][j], al[i], bh[j], acc[i][j]);
                }
        }
        __syncthreads();
    }

    // epilogue via smem staging
    float* sC = (float*)smem;
#pragma unroll
    for (int i = 0; i < 2; i++)
#pragma unroll
        for (int j = 0; j < 4; j++)
            wmma::store_matrix_sync(sC + (wm * 32 + i * 16) * 128 + wn * 64 + j * 16,
                                    acc[i][j], 128, wmma::mem_row_major);
    __syncthreads();
#pragma unroll
    for (int i = 0; i < 16; i++) {
        const int f = i * 256 + tid;
        const int r = f >> 5, c4 = f & 31;
        const int gm = rowA0 + r;
        if (gm < M) {
            float4 v = *(float4*)(sC + r * 128 + c4 * 4);
            const int n = n0 + c4 * 4;
            v.x += bias[n + 0];
            v.y += bias[n + 1];
            v.z += bias[n + 2];
            v.w += bias[n + 3];
            *(float4*)(C + (size_t)gm * N + n) = v;
        }
    }
}

// ---------------- inter_cls: 1 query (cls, Wq) over all 1569 tokens ----------
__global__ void inter_cls_kernel() {
    __shared__ float sc[SS];
    __shared__ float red[256];
    __shared__ float part[8 * D3];
    const int h = blockIdx.x, b = blockIdx.y;
    const int tid = threadIdx.x, lane = tid & 31, wid = tid >> 5;
    const float* baseq = g_xq + (size_t)b * SS * C3 + h * D3;
    const float* basek = g_xk + (size_t)b * SS * C3 + h * D3;
    const float* basev = g_xv + (size_t)b * SS * C3 + h * D3;

    float qv[6];
#pragma unroll
    for (int i = 0; i < 6; i++) qv[i] = baseq[lane + 32 * i];

    for (int t = wid; t < SS; t += 8) {
        const float* kr = basek + (size_t)t * C3;
        float p = 0.f;
#pragma unroll
        for (int i = 0; i < 6; i++) p += qv[i] * kr[lane + 32 * i];
#pragma unroll
        for (int off = 16; off; off >>= 1) p += __shfl_xor_sync(0xffffffffu, p, off);
        if (lane == 0) sc[t] = p * SCALE_INV;
    }
    __syncthreads();

    float m = -1e30f;
    for (int t = tid; t < SS; t += 256) m = fmaxf(m, sc[t]);
    red[tid] = m; __syncthreads();
    for (int s = 128; s; s >>= 1) { if (tid < s) red[tid] = fmaxf(red[tid], red[tid + s]); __syncthreads(); }
    m = red[0]; __syncthreads();

    float z = 0.f;
    for (int t = tid; t < SS; t += 256) { float e = expf(sc[t] - m); sc[t] = e; z += e; }
    red[tid] = z; __syncthreads();
    for (int s = 128; s; s >>= 1) { if (tid < s) red[tid] += red[tid + s]; __syncthreads(); }
    const float invZ = 1.f / red[0];
    __syncthreads();

    float a[6] = {0.f, 0.f, 0.f, 0.f, 0.f, 0.f};
    for (int t = wid; t < SS; t += 8) {
        const float p = sc[t];
        const float* vr = basev + (size_t)t * C3;
#pragma unroll
        for (int i = 0; i < 6; i++) a[i] += p * vr[lane + 32 * i];
    }
#pragma unroll
    for (int i = 0; i < 6; i++) part[wid * D3 + lane + 32 * i] = a[i];
    __syncthreads();
    if (tid < D3) {
        float s = 0.f;
#pragma unroll
        for (int w = 0; w < 8; w++) s += part[w * D3 + tid];
        g_cls[b * C3 + h * D3 + tid] = s * invZ;
    }
}

// ---------------- temporal attention per patch (8x8 over frames) -------------
__global__ void temporal_kernel() {
    __shared__ float qs[8 * 193];
    __shared__ float ks[8 * 193];
    __shared__ float sc[8 * 9];
    __shared__ float cw[8];
    const int p = blockIdx.x, h = blockIdx.y, b = blockIdx.z;
    const int tid = threadIdx.x;
    const size_t bb = (size_t)b * SS * C3;

    for (int e = tid; e < 8 * D3; e += 192) {
        int f = e / D3, j = e - f * D3;
        int tok = f * NP + p + 2;
        qs[f * 193 + j] = g_xq[bb + (size_t)tok * C3 + h * D3 + j];
        ks[f * 193 + j] = g_xv[bb + (size_t)tok * C3 + h * D3 + j];
    }
    __syncthreads();

    if (tid < 64) {
        int f = tid >> 3, g = tid & 7;
        float s = 0.f;
        for (int j = 0; j < D3; j++) s += qs[f * 193 + j] * ks[g * 193 + j];
        sc[f * 9 + g] = s * SCALE_INV;
    }
    __syncthreads();

    if (tid < 8) {
        int f = tid;
        float mx = -1e30f;
        for (int g = 0; g < 8; g++) mx = fmaxf(mx, sc[f * 9 + g]);
        float z = 0.f;
        for (int g = 0; g < 8; g++) { float e = expf(sc[f * 9 + g] - mx); sc[f * 9 + g] = e; z += e; }
        float inv = 1.f / z;
        for (int g = 0; g < 8; g++) sc[f * 9 + g] *= inv;
    }
    __syncthreads();
    if (tid < 8) {
        int g = tid;
        float s = 0.f;
        for (int f = 0; f < 8; f++) s += sc[f * 9 + g];
        cw[g] = s;
    }
    __syncthreads();

    {
        int d = tid;
        float acc = 0.f;
#pragma unroll
        for (int g = 0; g < 8; g++) {
            int tok = g * NP + p + 2;
            acc += cw[g] * g_xk[bb + (size_t)tok * C3 + h * D3 + d];
        }
        g_t1[((size_t)b * PP + p) * C3 + h * D3 + d] = acc;
    }
}

// ---------------- output-stage attention (column-weight trick) ---------------
__global__ void out_attn_kernel(int xi_base, int nk) {
    extern __shared__ float sm[];
    float* Kb = sm;
    float* qb = sm + nk * 193;
    float* w  = qb + 8 * D3;
    const int xi = xi_base + blockIdx.x;
    const int h = blockIdx.y, b = blockIdx.z;
    const int tid = threadIdx.x, lane = tid & 31, wid = tid >> 5;
    const size_t rbase = (size_t)b * PP * C3 + h * D3;

    for (int e = tid; e < nk * D3; e += 256) {
        int r = e / D3, j = e - r * D3;
        int kp = (nk == 196) ? (r % PP) : (xi + r);
        Kb[r * 193 + j] = g_k2[rbase + (size_t)kp * C3 + j];
    }
    for (int k = tid; k < nk; k += 256) w[k] = 0.f;
    __syncthreads();

    for (int q = wid; q < 196; q += 8) {
        int qp = (xi + q) % PP;
        for (int j = lane; j < D3; j += 32)
            qb[wid * D3 + j] = g_q2[rbase + (size_t)qp * C3 + j];
        __syncwarp();

        float s[7];
        int cnt = 0;
        for (int k = lane; k < nk; k += 32) {
            float d = 0.f;
            const float* kr = Kb + k * 193;
            const float* qr = qb + wid * D3;
            for (int j = 0; j < D3; j++) d += qr[j] * kr[j];
            s[cnt++] = d * SCALE_INV;
        }
        float mx = -1e30f;
        for (int c = 0; c < cnt; c++) mx = fmaxf(mx, s[c]);
#pragma unroll
        for (int off = 16; off; off >>= 1) mx = fmaxf(mx, __shfl_xor_sync(0xffffffffu, mx, off));
        float z = 0.f;
        for (int c = 0; c < cnt; c++) { float e = expf(s[c] - mx); s[c] = e; z += e; }
#pragma unroll
        for (int off = 16; off; off >>= 1) z += __shfl_xor_sync(0xffffffffu, z, off);
        float inv = 1.f / z;
        int c = 0;
        for (int k = lane; k < nk; k += 32, c++) atomicAdd(&w[k], s[c] * inv);
        __syncwarp();
    }
    __syncthreads();

    if (tid < D3) {
        float acc = 0.f;
        for (int k = 0; k < nk; k++) {
            int kp = (nk == 196) ? (k % PP) : (xi + k);
            acc += w[k] * g_v2[rbase + (size_t)kp * C3 + tid];
        }
        g_t2[((size_t)b * FF + xi) * C3 + h * D3 + tid] = acc;
    }
}

// ---------------- final 9 rows per batch: A(9x2304) @ Wf + bf ----------------
__global__ void final_rows_kernel(const float* __restrict__ Wf, const float* __restrict__ bf) {
    extern __shared__ float As[];
    const int cb = blockIdx.x, b = blockIdx.y;
    const int tid = threadIdx.x;
    for (int e = tid; e < 9 * C3; e += 192) {
        int r = e / C3, k = e - r * C3;
        As[e] = (r == 0) ? g_cls[b * C3 + k] : g_t2[((size_t)b * FF + (r - 1)) * C3 + k];
    }
    __syncthreads();
    const int c = cb * 192 + tid;
    float acc[9];
#pragma unroll
    for (int r = 0; r < 9; r++) acc[r] = 0.f;
    for (int k = 0; k < C3; k++) {
        float wv = Wf[(size_t)k * DIMM + c];
#pragma unroll
        for (int r = 0; r < 9; r++) acc[r] += As[r * C3 + k] * wv;
    }
    float bv = bf[c];
#pragma unroll
    for (int r = 0; r < 9; r++)
        g_rows[((size_t)b * 9 + r) * DIMM + c] = acc[r] + bv;
}

// ---------------- broadcast 9 rows -> (B, 1569, 768) output -----------------
__global__ void bcast_kernel(float* __restrict__ out) {
    size_t i4 = (size_t)blockIdx.x * blockDim.x + threadIdx.x;
    const size_t total4 = (size_t)BB * SS * DIMM / 4;
    if (i4 >= total4) return;
    size_t idx = i4 * 4;
    int c = idx % DIMM;
    size_t rs = idx / DIMM;
    int s = rs % SS;
    int b = rs / SS;
    int r = (s == 0) ? 0 : 1 + ((s - 1) & 7);
    ((float4*)out)[i4] = *(const float4*)(g_rows + ((size_t)b * 9 + r) * DIMM + c);
}

// ---------------- launch ------------------------------------------------------
extern "C" void kernel_launch(void* const* d_in, const int* in_sizes, int n_in,
                              void* d_out, int out_size) {
    const float* x  = (const float*)d_in[0];
    const float* Wq = (const float*)d_in[1];
    const float* bq = (const float*)d_in[2];
    const float* Wk = (const float*)d_in[3];
    const float* bk = (const float*)d_in[4];
    const float* Wv = (const float*)d_in[5];
    const float* bv = (const float*)d_in[6];
    const float* Wt = (const float*)d_in[7];
    const float* bt = (const float*)d_in[8];
    const float* Wf = (const float*)d_in[9];
    const float* bf = (const float*)d_in[10];
    float* out = (float*)d_out;

    float *p_xq, *p_xk, *p_xv, *p_t1, *p_ti, *p_q2, *p_k2, *p_v2;
    cudaGetSymbolAddress((void**)&p_xq, g_xq);
    cudaGetSymbolAddress((void**)&p_xk, g_xk);
    cudaGetSymbolAddress((void**)&p_xv, g_xv);
    cudaGetSymbolAddress((void**)&p_t1, g_t1);
    cudaGetSymbolAddress((void**)&p_ti, g_ti);
    cudaGetSymbolAddress((void**)&p_q2, g_q2);
    cudaGetSymbolAddress((void**)&p_k2, g_k2);
    cudaGetSymbolAddress((void**)&p_v2, g_v2);
    __nv_bfloat16 *p_xhi, *p_xlo, *p_t1hi, *p_t1lo, *p_tihi, *p_tilo;
    __nv_bfloat16 *p_Wqhi, *p_Wqlo, *p_Wkhi, *p_Wklo, *p_Wvhi, *p_Wvlo, *p_Wthi, *p_Wtlo;
    cudaGetSymbolAddress((void**)&p_xhi, g_xhi);
    cudaGetSymbolAddress((void**)&p_xlo, g_xlo);
    cudaGetSymbolAddress((void**)&p_t1hi, g_t1hi);
    cudaGetSymbolAddress((void**)&p_t1lo, g_t1lo);
    cudaGetSymbolAddress((void**)&p_tihi, g_tihi);
    cudaGetSymbolAddress((void**)&p_tilo, g_tilo);
    cudaGetSymbolAddress((void**)&p_Wqhi, g_WqThi);
    cudaGetSymbolAddress((void**)&p_Wqlo, g_WqTlo);
    cudaGetSymbolAddress((void**)&p_Wkhi, g_WkThi);
    cudaGetSymbolAddress((void**)&p_Wklo, g_WkTlo);
    cudaGetSymbolAddress((void**)&p_Wvhi, g_WvThi);
    cudaGetSymbolAddress((void**)&p_Wvlo, g_WvTlo);
    cudaGetSymbolAddress((void**)&p_Wthi, g_WtThi);
    cudaGetSymbolAddress((void**)&p_Wtlo, g_WtTlo);

    const size_t GEMM_SMEM = (size_t)NSTAGE * STAGE_B;  // 122880
    cudaFuncSetAttribute(gemm_bs, cudaFuncAttributeMaxDynamicSharedMemorySize, (int)GEMM_SMEM);
    cudaFuncSetAttribute(out_attn_kernel, cudaFuncAttributeMaxDynamicSharedMemorySize, 160000);
    cudaFuncSetAttribute(final_rows_kernel, cudaFuncAttributeMaxDynamicSharedMemorySize, 9 * C3 * 4);

    // weights: transpose + split
    transpose_split<<<dim3(C3 / 32, DIMM / 32), 256>>>(Wq, p_Wqhi, p_Wqlo, DIMM, C3);
    transpose_split<<<dim3(C3 / 32, DIMM / 32), 256>>>(Wk, p_Wkhi, p_Wklo, DIMM, C3);
    transpose_split<<<dim3(C3 / 32, DIMM / 32), 256>>>(Wv, p_Wvhi, p_Wvlo, DIMM, C3);
    transpose_split<<<dim3(DIMM / 32, C3 / 32), 256>>>(Wt, p_Wthi, p_Wtlo, C3, DIMM);
    // x split
    {
        int n4 = BB * SS * DIMM / 4;
        split_f32<<<(n4 + 255) / 256, 256>>>(x, p_xhi, p_xlo, n4);
    }

    const int M1 = BB * SS;   // 12552
    {
        dim3 grid(C3 / 128, M1PAD / 128);
        gemm_bs<<<grid, 256, GEMM_SMEM>>>(p_xhi, p_xlo, p_Wqhi, p_Wqlo, bq, p_xq, M1, C3, DIMM);
        gemm_bs<<<grid, 256, GEMM_SMEM>>>(p_xhi, p_xlo, p_Wkhi, p_Wklo, bk, p_xk, M1, C3, DIMM);
        gemm_bs<<<grid, 256, GEMM_SMEM>>>(p_xhi, p_xlo, p_Wvhi, p_Wvlo, bv, p_xv, M1, C3, DIMM);
    }
    inter_cls_kernel<<<dim3(HH, BB), 256>>>();
    temporal_kernel<<<dim3(PP, HH, BB), 192>>>();

    const int M2 = BB * PP;   // 1560
    {
        int n4 = M2 * C3 / 4;
        split_f32<<<(n4 + 255) / 256, 256>>>(p_t1, p_t1hi, p_t1lo, n4);
        dim3 grid(DIMM / 128, M2PAD / 128);
        gemm_bs<<<grid, 256, GEMM_SMEM>>>(p_t1hi, p_t1lo, p_Wthi, p_Wtlo, bt, p_ti, M2, DIMM, C3);
    }
    {
        int n4 = M2 * DIMM / 4;
        split_f32<<<(n4 + 255) / 256, 256>>>(p_ti, p_tihi, p_tilo, n4);
        dim3 grid(C3 / 128, M2PAD / 128);
        gemm_bs<<<grid, 256, GEMM_SMEM>>>(p_tihi, p_tilo, p_Wqhi, p_Wqlo, bq, p_q2, M2, C3, DIMM);
        gemm_bs<<<grid, 256, GEMM_SMEM>>>(p_tihi, p_tilo, p_Wvhi, p_Wvlo, bv, p_k2, M2, C3, DIMM);  // k2
        gemm_bs<<<grid, 256, GEMM_SMEM>>>(p_tihi, p_tilo, p_Wkhi, p_Wklo, bk, p_v2, M2, C3, DIMM);  // v2
    }
    {
        size_t smA = (size_t)(196 * 193 + 8 * D3 + 196) * 4;
        out_attn_kernel<<<dim3(1, HH, BB), 256, smA>>>(0, 196);
        size_t smB = (size_t)(8 * 193 + 8 * D3 + 8) * 4;
        out_attn_kernel<<<dim3(7, HH, BB), 256, smB>>>(1, 8);
    }
    final_rows_kernel<<<dim3(4, BB), 192, (size_t)9 * C3 * 4>>>(Wf, bf);
    {
        const size_t total4 = (size_t)BB * SS * DIMM / 4;
        bcast_kernel<<<(unsigned)((total4 + 255) / 256), 256>>>(out);
    }
}

// round 5
// speedup vs baseline: 1.6224x; 1.1113x over previous
#include <cuda_runtime.h>
#include <cuda_bf16.h>
#include <mma.h>
#include <cstdint>
#include <math.h>

using namespace nvcuda;

#define HH 12
#define NP 196
#define FF 8
#define DIMM 768
#define D3 192
#define BB 8
#define SS 1569
#define PP 195
#define C3 2304
#define SCALE_INV (1.0f/96.0f)

#define M1PAD 12672   // ceil(8*1569/128)*128
#define M2PAD 1664    // ceil(8*195/128)*128

// ---------------- scratch (device globals; zero-initialized) ----------------
__device__ float g_xq[BB*SS*C3];
__device__ float g_xk[BB*SS*C3];
__device__ float g_xv[BB*SS*C3];
__device__ float g_t1[BB*PP*C3];
__device__ float g_ti[BB*PP*DIMM];
__device__ float g_q2[BB*PP*C3];
__device__ float g_k2[BB*PP*C3];
__device__ float g_v2[BB*PP*C3];
__device__ float g_cls[BB*C3];
__device__ float g_t2[BB*FF*C3];
__device__ float g_rows[BB*9*DIMM];
// bf16 hi/lo split buffers (A-side, padded rows)
__device__ __nv_bfloat16 g_xhi[M1PAD*DIMM],  g_xlo[M1PAD*DIMM];
__device__ __nv_bfloat16 g_t1hi[M2PAD*C3],   g_t1lo[M2PAD*C3];
__device__ __nv_bfloat16 g_tihi[M2PAD*DIMM], g_tilo[M2PAD*DIMM];
// bf16 hi/lo transposed weights [N,K]
__device__ __nv_bfloat16 g_WqThi[C3*DIMM], g_WqTlo[C3*DIMM];
__device__ __nv_bfloat16 g_WkThi[C3*DIMM], g_WkTlo[C3*DIMM];
__device__ __nv_bfloat16 g_WvThi[C3*DIMM], g_WvTlo[C3*DIMM];
__device__ __nv_bfloat16 g_WtThi[DIMM*C3], g_WtTlo[DIMM*C3];

// ---------------- cp.async helpers ------------------------------------------
__device__ __forceinline__ uint32_t smem_u32(const void* p) {
    uint32_t a;
    asm("{ .reg .u64 t; cvta.to.shared.u64 t, %1; cvt.u32.u64 %0, t; }" : "=r"(a) : "l"(p));
    return a;
}
#define CP_ASYNC16(dst_u32, src_ptr) \
    asm volatile("cp.async.cg.shared.global [%0], [%1], 16;" :: "r"(dst_u32), "l"(src_ptr))
#define CP_COMMIT() asm volatile("cp.async.commit_group;" ::: "memory")
#define CP_WAIT1()  asm volatile("cp.async.wait_group 1;" ::: "memory")

// ---------------- split: fp32 -> bf16 hi + bf16 lo --------------------------
__global__ void split_f32(const float* __restrict__ in, __nv_bfloat16* __restrict__ hi,
                          __nv_bfloat16* __restrict__ lo, int n4) {
    int i = blockIdx.x * blockDim.x + threadIdx.x;
    if (i >= n4) return;
    float4 v = ((const float4*)in)[i];
    __nv_bfloat16 h0 = __float2bfloat16(v.x), h1 = __float2bfloat16(v.y);
    __nv_bfloat16 h2 = __float2bfloat16(v.z), h3 = __float2bfloat16(v.w);
    __nv_bfloat162 lo01(__float2bfloat16(v.x - __bfloat162float(h0)),
                        __float2bfloat16(v.y - __bfloat162float(h1)));
    __nv_bfloat162 lo23(__float2bfloat16(v.z - __bfloat162float(h2)),
                        __float2bfloat16(v.w - __bfloat162float(h3)));
    ((__nv_bfloat162*)hi)[i * 2 + 0] = __nv_bfloat162(h0, h1);
    ((__nv_bfloat162*)hi)[i * 2 + 1] = __nv_bfloat162(h2, h3);
    ((__nv_bfloat162*)lo)[i * 2 + 0] = lo01;
    ((__nv_bfloat162*)lo)[i * 2 + 1] = lo23;
}

// ---------------- transpose + split: fp32 [K,N] -> bf16 hi/lo [N,K] ---------
__global__ void transpose_split(const float* __restrict__ in,
                                __nv_bfloat16* __restrict__ hi,
                                __nv_bfloat16* __restrict__ lo, int K, int N) {
    __shared__ float t[32][33];
    const int n0 = blockIdx.x * 32, k0 = blockIdx.y * 32;
    const int tx = threadIdx.x & 31, ty = threadIdx.x >> 5;
#pragma unroll
    for (int i = 0; i < 32; i += 8)
        t[ty + i][tx] = in[(size_t)(k0 + ty + i) * N + n0 + tx];
    __syncthreads();
#pragma unroll
    for (int i = 0; i < 32; i += 8) {
        float v = t[tx][ty + i];
        __nv_bfloat16 h = __float2bfloat16(v);
        hi[(size_t)(n0 + ty + i) * K + k0 + tx] = h;
        lo[(size_t)(n0 + ty + i) * K + k0 + tx] = __float2bfloat16(v - __bfloat162float(h));
    }
}

// ================= bf16-split HMMA GEMM, 2-stage cp.async, 2 CTA/SM =========
// C(MxN) = [Ahi+Alo](MxK) @ [Bhi+Blo]([N,K])^T + bias, 3-pass fp32 accumulate.
#define LDT 40
#define TILE_B (128 * LDT * 2)        // 10240 bytes per bf16 tile
#define STAGE_B (4 * TILE_B)          // 40960 bytes per stage
#define NSTAGE 2

__global__ void __launch_bounds__(256, 2)
gemm_bs(const __nv_bfloat16* __restrict__ Ahi, const __nv_bfloat16* __restrict__ Alo,
        const __nv_bfloat16* __restrict__ Bhi, const __nv_bfloat16* __restrict__ Blo,
        const float* __restrict__ bias, float* __restrict__ C,
        int M, int N, int K) {
    extern __shared__ char smem[];
    const uint32_t smem_b = smem_u32(smem);
    const int tid = threadIdx.x;
    const int wid = tid >> 5;
    const int wm = wid & 3, wn = wid >> 2;
    const int rowA0 = blockIdx.y * 128;
    const int n0 = blockIdx.x * 128;
    const int nch = K >> 5;

    // per-thread cp.async coordinates: 2 ops per tile, 8 ops per stage
    const int r_cp = tid >> 1;              // 0..127
    const int s_cp = (tid & 1) * 2;         // 0 or 2
    const __nv_bfloat16* srcs[4];
    srcs[0] = Ahi + (size_t)(rowA0 + r_cp) * K;
    srcs[1] = Alo + (size_t)(rowA0 + r_cp) * K;
    srcs[2] = Bhi + (size_t)(n0 + r_cp) * K;
    srcs[3] = Blo + (size_t)(n0 + r_cp) * K;
    const uint32_t dst_row = smem_b + r_cp * (LDT * 2);

    auto issue_stage = [&](int c, int buf) {
        const int k0 = c << 5;
        const uint32_t sb = buf * STAGE_B;
#pragma unroll
        for (int t = 0; t < 4; t++) {
            const __nv_bfloat16* src = srcs[t] + k0 + s_cp * 8;
            const uint32_t dst = dst_row + sb + t * TILE_B + s_cp * 16;
            CP_ASYNC16(dst, src);
            CP_ASYNC16(dst + 16, src + 8);
        }
    };

    wmma::fragment<wmma::accumulator, 16, 16, 16, float> acc[2][4];
#pragma unroll
    for (int i = 0; i < 2; i++)
#pragma unroll
        for (int j = 0; j < 4; j++) wmma::fill_fragment(acc[i][j], 0.f);

    // prologue: stage 0
    issue_stage(0, 0);
    CP_COMMIT();

    for (int c = 0; c < nch; c++) {
        if (c + 1 < nch) issue_stage(c + 1, (c + 1) & 1);
        CP_COMMIT();
        CP_WAIT1();
        __syncthreads();

        const __nv_bfloat16* Ah = (const __nv_bfloat16*)(smem + (c & 1) * STAGE_B);
        const __nv_bfloat16* Al = Ah + 128 * LDT;
        const __nv_bfloat16* Bh = Al + 128 * LDT;
        const __nv_bfloat16* Bl = Bh + 128 * LDT;
#pragma unroll
        for (int kk = 0; kk < 32; kk += 16) {
            wmma::fragment<wmma::matrix_a, 16, 16, 16, __nv_bfloat16, wmma::row_major> ah[2], al[2];
#pragma unroll
            for (int i = 0; i < 2; i++) {
                wmma::load_matrix_sync(ah[i], Ah + (wm * 32 + i * 16) * LDT + kk, LDT);
                wmma::load_matrix_sync(al[i], Al + (wm * 32 + i * 16) * LDT + kk, LDT);
            }
#pragma unroll
            for (int j = 0; j < 4; j++) {
                wmma::fragment<wmma::matrix_b, 16, 16, 16, __nv_bfloat16, wmma::col_major> bh, bl;
                wmma::load_matrix_sync(bh, Bh + (wn * 64 + j * 16) * LDT + kk, LDT);
                wmma::load_matrix_sync(bl, Bl + (wn * 64 + j * 16) * LDT + kk, LDT);
#pragma unroll
                for (int i = 0; i < 2; i++) {
                    wmma::mma_sync(acc[i][j], ah[i], bh, acc[i][j]);
                    wmma::mma_sync(acc[i][j], ah[i], bl, acc[i][j]);
                    wmma::mma_sync(acc[i][j], al[i], bh, acc[i][j]);
                }
            }
        }
        __syncthreads();
    }

    // epilogue via smem staging
    float* sC = (float*)smem;
#pragma unroll
    for (int i = 0; i < 2; i++)
#pragma unroll
        for (int j = 0; j < 4; j++)
            wmma::store_matrix_sync(sC + (wm * 32 + i * 16) * 128 + wn * 64 + j * 16,
                                    acc[i][j], 128, wmma::mem_row_major);
    __syncthreads();
#pragma unroll
    for (int i = 0; i < 16; i++) {
        const int f = i * 256 + tid;
        const int r = f >> 5, c4 = f & 31;
        const int gm = rowA0 + r;
        if (gm < M) {
            float4 v = *(float4*)(sC + r * 128 + c4 * 4);
            const int n = n0 + c4 * 4;
            v.x += bias[n + 0];
            v.y += bias[n + 1];
            v.z += bias[n + 2];
            v.w += bias[n + 3];
            *(float4*)(C + (size_t)gm * N + n) = v;
        }
    }
}

// ---------------- inter_cls: 1 query (cls, Wq) over all 1569 tokens ----------
__global__ void inter_cls_kernel() {
    __shared__ float sc[SS];
    __shared__ float red[256];
    __shared__ float part[8 * D3];
    const int h = blockIdx.x, b = blockIdx.y;
    const int tid = threadIdx.x, lane = tid & 31, wid = tid >> 5;
    const float* baseq = g_xq + (size_t)b * SS * C3 + h * D3;
    const float* basek = g_xk + (size_t)b * SS * C3 + h * D3;
    const float* basev = g_xv + (size_t)b * SS * C3 + h * D3;

    float qv[6];
#pragma unroll
    for (int i = 0; i < 6; i++) qv[i] = baseq[lane + 32 * i];

    for (int t = wid; t < SS; t += 8) {
        const float* kr = basek + (size_t)t * C3;
        float p = 0.f;
#pragma unroll
        for (int i = 0; i < 6; i++) p += qv[i] * kr[lane + 32 * i];
#pragma unroll
        for (int off = 16; off; off >>= 1) p += __shfl_xor_sync(0xffffffffu, p, off);
        if (lane == 0) sc[t] = p * SCALE_INV;
    }
    __syncthreads();

    float m = -1e30f;
    for (int t = tid; t < SS; t += 256) m = fmaxf(m, sc[t]);
    red[tid] = m; __syncthreads();
    for (int s = 128; s; s >>= 1) { if (tid < s) red[tid] = fmaxf(red[tid], red[tid + s]); __syncthreads(); }
    m = red[0]; __syncthreads();

    float z = 0.f;
    for (int t = tid; t < SS; t += 256) { float e = expf(sc[t] - m); sc[t] = e; z += e; }
    red[tid] = z; __syncthreads();
    for (int s = 128; s; s >>= 1) { if (tid < s) red[tid] += red[tid + s]; __syncthreads(); }
    const float invZ = 1.f / red[0];
    __syncthreads();

    float a[6] = {0.f, 0.f, 0.f, 0.f, 0.f, 0.f};
    for (int t = wid; t < SS; t += 8) {
        const float p = sc[t];
        const float* vr = basev + (size_t)t * C3;
#pragma unroll
        for (int i = 0; i < 6; i++) a[i] += p * vr[lane + 32 * i];
    }
#pragma unroll
    for (int i = 0; i < 6; i++) part[wid * D3 + lane + 32 * i] = a[i];
    __syncthreads();
    if (tid < D3) {
        float s = 0.f;
#pragma unroll
        for (int w = 0; w < 8; w++) s += part[w * D3 + tid];
        g_cls[b * C3 + h * D3 + tid] = s * invZ;
    }
}

// ---------------- temporal attention per patch (8x8 over frames) -------------
__global__ void temporal_kernel() {
    __shared__ float qs[8 * 193];
    __shared__ float ks[8 * 193];
    __shared__ float sc[8 * 9];
    __shared__ float cw[8];
    const int p = blockIdx.x, h = blockIdx.y, b = blockIdx.z;
    const int tid = threadIdx.x;
    const size_t bb = (size_t)b * SS * C3;

    for (int e = tid; e < 8 * D3; e += 192) {
        int f = e / D3, j = e - f * D3;
        int tok = f * NP + p + 2;
        qs[f * 193 + j] = g_xq[bb + (size_t)tok * C3 + h * D3 + j];
        ks[f * 193 + j] = g_xv[bb + (size_t)tok * C3 + h * D3 + j];
    }
    __syncthreads();

    if (tid < 64) {
        int f = tid >> 3, g = tid & 7;
        float s = 0.f;
        for (int j = 0; j < D3; j++) s += qs[f * 193 + j] * ks[g * 193 + j];
        sc[f * 9 + g] = s * SCALE_INV;
    }
    __syncthreads();

    if (tid < 8) {
        int f = tid;
        float mx = -1e30f;
        for (int g = 0; g < 8; g++) mx = fmaxf(mx, sc[f * 9 + g]);
        float z = 0.f;
        for (int g = 0; g < 8; g++) { float e = expf(sc[f * 9 + g] - mx); sc[f * 9 + g] = e; z += e; }
        float inv = 1.f / z;
        for (int g = 0; g < 8; g++) sc[f * 9 + g] *= inv;
    }
    __syncthreads();
    if (tid < 8) {
        int g = tid;
        float s = 0.f;
        for (int f = 0; f < 8; f++) s += sc[f * 9 + g];
        cw[g] = s;
    }
    __syncthreads();

    {
        int d = tid;
        float acc = 0.f;
#pragma unroll
        for (int g = 0; g < 8; g++) {
            int tok = g * NP + p + 2;
            acc += cw[g] * g_xk[bb + (size_t)tok * C3 + h * D3 + d];
        }
        g_t1[((size_t)b * PP + p) * C3 + h * D3 + d] = acc;
    }
}

// ---------------- output-stage attention (column-weight trick) ---------------
__global__ void out_attn_kernel(int xi_base, int nk) {
    extern __shared__ float sm[];
    float* Kb = sm;
    float* qb = sm + nk * 193;
    float* w  = qb + 8 * D3;
    const int xi = xi_base + blockIdx.x;
    const int h = blockIdx.y, b = blockIdx.z;
    const int tid = threadIdx.x, lane = tid & 31, wid = tid >> 5;
    const size_t rbase = (size_t)b * PP * C3 + h * D3;

    for (int e = tid; e < nk * D3; e += 256) {
        int r = e / D3, j = e - r * D3;
        int kp = (nk == 196) ? (r % PP) : (xi + r);
        Kb[r * 193 + j] = g_k2[rbase + (size_t)kp * C3 + j];
    }
    for (int k = tid; k < nk; k += 256) w[k] = 0.f;
    __syncthreads();

    for (int q = wid; q < 196; q += 8) {
        int qp = (xi + q) % PP;
        for (int j = lane; j < D3; j += 32)
            qb[wid * D3 + j] = g_q2[rbase + (size_t)qp * C3 + j];
        __syncwarp();

        float s[7];
        int cnt = 0;
        for (int k = lane; k < nk; k += 32) {
            float d = 0.f;
            const float* kr = Kb + k * 193;
            const float* qr = qb + wid * D3;
            for (int j = 0; j < D3; j++) d += qr[j] * kr[j];
            s[cnt++] = d * SCALE_INV;
        }
        float mx = -1e30f;
        for (int c = 0; c < cnt; c++) mx = fmaxf(mx, s[c]);
#pragma unroll
        for (int off = 16; off; off >>= 1) mx = fmaxf(mx, __shfl_xor_sync(0xffffffffu, mx, off));
        float z = 0.f;
        for (int c = 0; c < cnt; c++) { float e = expf(s[c] - mx); s[c] = e; z += e; }
#pragma unroll
        for (int off = 16; off; off >>= 1) z += __shfl_xor_sync(0xffffffffu, z, off);
        float inv = 1.f / z;
        int c = 0;
        for (int k = lane; k < nk; k += 32, c++) atomicAdd(&w[k], s[c] * inv);
        __syncwarp();
    }
    __syncthreads();

    if (tid < D3) {
        float acc = 0.f;
        for (int k = 0; k < nk; k++) {
            int kp = (nk == 196) ? (k % PP) : (xi + k);
            acc += w[k] * g_v2[rbase + (size_t)kp * C3 + tid];
        }
        g_t2[((size_t)b * FF + xi) * C3 + h * D3 + tid] = acc;
    }
}

// ---------------- final 9 rows per batch: A(9x2304) @ Wf + bf ----------------
__global__ void final_rows_kernel(const float* __restrict__ Wf, const float* __restrict__ bf) {
    extern __shared__ float As[];
    const int cb = blockIdx.x, b = blockIdx.y;
    const int tid = threadIdx.x;
    for (int e = tid; e < 9 * C3; e += 192) {
        int r = e / C3, k = e - r * C3;
        As[e] = (r == 0) ? g_cls[b * C3 + k] : g_t2[((size_t)b * FF + (r - 1)) * C3 + k];
    }
    __syncthreads();
    const int c = cb * 192 + tid;
    float acc[9];
#pragma unroll
    for (int r = 0; r < 9; r++) acc[r] = 0.f;
    for (int k = 0; k < C3; k++) {
        float wv = Wf[(size_t)k * DIMM + c];
#pragma unroll
        for (int r = 0; r < 9; r++) acc[r] += As[r * C3 + k] * wv;
    }
    float bv = bf[c];
#pragma unroll
    for (int r = 0; r < 9; r++)
        g_rows[((size_t)b * 9 + r) * DIMM + c] = acc[r] + bv;
}

// ---------------- broadcast 9 rows -> (B, 1569, 768) output -----------------
__global__ void bcast_kernel(float* __restrict__ out) {
    size_t i4 = (size_t)blockIdx.x * blockDim.x + threadIdx.x;
    const size_t total4 = (size_t)BB * SS * DIMM / 4;
    if (i4 >= total4) return;
    size_t idx = i4 * 4;
    int c = idx % DIMM;
    size_t rs = idx / DIMM;
    int s = rs % SS;
    int b = rs / SS;
    int r = (s == 0) ? 0 : 1 + ((s - 1) & 7);
    ((float4*)out)[i4] = *(const float4*)(g_rows + ((size_t)b * 9 + r) * DIMM + c);
}

// ---------------- launch ------------------------------------------------------
extern "C" void kernel_launch(void* const* d_in, const int* in_sizes, int n_in,
                              void* d_out, int out_size) {
    const float* x  = (const float*)d_in[0];
    const float* Wq = (const float*)d_in[1];
    const float* bq = (const float*)d_in[2];
    const float* Wk = (const float*)d_in[3];
    const float* bk = (const float*)d_in[4];
    const float* Wv = (const float*)d_in[5];
    const float* bv = (const float*)d_in[6];
    const float* Wt = (const float*)d_in[7];
    const float* bt = (const float*)d_in[8];
    const float* Wf = (const float*)d_in[9];
    const float* bf = (const float*)d_in[10];
    float* out = (float*)d_out;

    float *p_xq, *p_xk, *p_xv, *p_t1, *p_ti, *p_q2, *p_k2, *p_v2;
    cudaGetSymbolAddress((void**)&p_xq, g_xq);
    cudaGetSymbolAddress((void**)&p_xk, g_xk);
    cudaGetSymbolAddress((void**)&p_xv, g_xv);
    cudaGetSymbolAddress((void**)&p_t1, g_t1);
    cudaGetSymbolAddress((void**)&p_ti, g_ti);
    cudaGetSymbolAddress((void**)&p_q2, g_q2);
    cudaGetSymbolAddress((void**)&p_k2, g_k2);
    cudaGetSymbolAddress((void**)&p_v2, g_v2);
    __nv_bfloat16 *p_xhi, *p_xlo, *p_t1hi, *p_t1lo, *p_tihi, *p_tilo;
    __nv_bfloat16 *p_Wqhi, *p_Wqlo, *p_Wkhi, *p_Wklo, *p_Wvhi, *p_Wvlo, *p_Wthi, *p_Wtlo;
    cudaGetSymbolAddress((void**)&p_xhi, g_xhi);
    cudaGetSymbolAddress((void**)&p_xlo, g_xlo);
    cudaGetSymbolAddress((void**)&p_t1hi, g_t1hi);
    cudaGetSymbolAddress((void**)&p_t1lo, g_t1lo);
    cudaGetSymbolAddress((void**)&p_tihi, g_tihi);
    cudaGetSymbolAddress((void**)&p_tilo, g_tilo);
    cudaGetSymbolAddress((void**)&p_Wqhi, g_WqThi);
    cudaGetSymbolAddress((void**)&p_Wqlo, g_WqTlo);
    cudaGetSymbolAddress((void**)&p_Wkhi, g_WkThi);
    cudaGetSymbolAddress((void**)&p_Wklo, g_WkTlo);
    cudaGetSymbolAddress((void**)&p_Wvhi, g_WvThi);
    cudaGetSymbolAddress((void**)&p_Wvlo, g_WvTlo);
    cudaGetSymbolAddress((void**)&p_Wthi, g_WtThi);
    cudaGetSymbolAddress((void**)&p_Wtlo, g_WtTlo);

    const size_t GEMM_SMEM = (size_t)NSTAGE * STAGE_B;  // 81920
    cudaFuncSetAttribute(gemm_bs, cudaFuncAttributeMaxDynamicSharedMemorySize, (int)GEMM_SMEM);
    cudaFuncSetAttribute(out_attn_kernel, cudaFuncAttributeMaxDynamicSharedMemorySize, 160000);
    cudaFuncSetAttribute(final_rows_kernel, cudaFuncAttributeMaxDynamicSharedMemorySize, 9 * C3 * 4);

    // weights: transpose + split
    transpose_split<<<dim3(C3 / 32, DIMM / 32), 256>>>(Wq, p_Wqhi, p_Wqlo, DIMM, C3);
    transpose_split<<<dim3(C3 / 32, DIMM / 32), 256>>>(Wk, p_Wkhi, p_Wklo, DIMM, C3);
    transpose_split<<<dim3(C3 / 32, DIMM / 32), 256>>>(Wv, p_Wvhi, p_Wvlo, DIMM, C3);
    transpose_split<<<dim3(DIMM / 32, C3 / 32), 256>>>(Wt, p_Wthi, p_Wtlo, C3, DIMM);
    // x split
    {
        int n4 = BB * SS * DIMM / 4;
        split_f32<<<(n4 + 255) / 256, 256>>>(x, p_xhi, p_xlo, n4);
    }

    const int M1 = BB * SS;   // 12552
    {
        dim3 grid(C3 / 128, M1PAD / 128);
        gemm_bs<<<grid, 256, GEMM_SMEM>>>(p_xhi, p_xlo, p_Wqhi, p_Wqlo, bq, p_xq, M1, C3, DIMM);
        gemm_bs<<<grid, 256, GEMM_SMEM>>>(p_xhi, p_xlo, p_Wkhi, p_Wklo, bk, p_xk, M1, C3, DIMM);
        gemm_bs<<<grid, 256, GEMM_SMEM>>>(p_xhi, p_xlo, p_Wvhi, p_Wvlo, bv, p_xv, M1, C3, DIMM);
    }
    inter_cls_kernel<<<dim3(HH, BB), 256>>>();
    temporal_kernel<<<dim3(PP, HH, BB), 192>>>();

    const int M2 = BB * PP;   // 1560
    {
        int n4 = M2 * C3 / 4;
        split_f32<<<(n4 + 255) / 256, 256>>>(p_t1, p_t1hi, p_t1lo, n4);
        dim3 grid(DIMM / 128, M2PAD / 128);
        gemm_bs<<<grid, 256, GEMM_SMEM>>>(p_t1hi, p_t1lo, p_Wthi, p_Wtlo, bt, p_ti, M2, DIMM, C3);
    }
    {
        int n4 = M2 * DIMM / 4;
        split_f32<<<(n4 + 255) / 256, 256>>>(p_ti, p_tihi, p_tilo, n4);
        dim3 grid(C3 / 128, M2PAD / 128);
        gemm_bs<<<grid, 256, GEMM_SMEM>>>(p_tihi, p_tilo, p_Wqhi, p_Wqlo, bq, p_q2, M2, C3, DIMM);
        gemm_bs<<<grid, 256, GEMM_SMEM>>>(p_tihi, p_tilo, p_Wvhi, p_Wvlo, bv, p_k2, M2, C3, DIMM);  // k2
        gemm_bs<<<grid, 256, GEMM_SMEM>>>(p_tihi, p_tilo, p_Wkhi, p_Wklo, bk, p_v2, M2, C3, DIMM);  // v2
    }
    {
        size_t smA = (size_t)(196 * 193 + 8 * D3 + 196) * 4;
        out_attn_kernel<<<dim3(1, HH, BB), 256, smA>>>(0, 196);
        size_t smB = (size_t)(8 * 193 + 8 * D3 + 8) * 4;
        out_attn_kernel<<<dim3(7, HH, BB), 256, smB>>>(1, 8);
    }
    final_rows_kernel<<<dim3(4, BB), 192, (size_t)9 * C3 * 4>>>(Wf, bf);
    {
        const size_t total4 = (size_t)BB * SS * DIMM / 4;
        bcast_kernel<<<(unsigned)((total4 + 255) / 256), 256>>>(out);
    }
}